// round 13
// baseline (speedup 1.0000x reference)
#include <cuda_runtime.h>
#include <cuda_bf16.h>
#include <stdint.h>
#include <math.h>

// RoIPool: input [N,256,50,50] f32, rois [R,5] f32, out [R,256,7,7] f32.
// spatial_scale=1/16; torchvision MaxRoiPool semantics (round-half-even,
// roi size >= 1, floor/ceil bin edges clipped to [0,W]/[0,H], empty bin -> 0).
//
// Design:
//  1) transpose NCHW -> NHWC (channels contiguous)
//  2) main: block=(roi, 128-channel half), 224 threads = 7 warps, warp=ph,
//     lane = channel-quad (float4) -> every window-cell access is LDG.128,
//     512B per warp-load, warp-uniform bin bounds (zero divergence).
//     Results staged in smem, written out as one contiguous coalesced block.

typedef unsigned int u32;

#define PH 7
#define PW 7
#define BINS 49
#define SCALE 0.0625f
#define C_ 256
#define H_ 50
#define W_ 50
#define HW_ (H_ * W_)
#define CHW_ (C_ * HW_)
#define MAXN 4
#define C4_ (C_ / 4)     // 64 float4 per cell

__device__ float g_inT[MAXN * HW_ * C_];   // [N][H][W][C]

// ---------------- transpose [N,C,HW] -> [N,HW,C] ----------------
__global__ void transpose_k(const float* __restrict__ in) {
    __shared__ float t[32][33];
    int b  = blockIdx.z;
    int s0 = blockIdx.x * 32;   // hw tile
    int c0 = blockIdx.y * 32;   // channel tile
    int x = threadIdx.x, y = threadIdx.y;

#pragma unroll
    for (int j = 0; j < 32; j += 8) {
        int c = c0 + y + j, s = s0 + x;
        if (s < HW_) t[y + j][x] = in[b * CHW_ + c * HW_ + s];
    }
    __syncthreads();
#pragma unroll
    for (int j = 0; j < 32; j += 8) {
        int s = s0 + y + j, c = c0 + x;
        if (s < HW_) g_inT[b * CHW_ + s * C_ + c] = t[x][y + j];
    }
}

// ---------------- main pooling ----------------
// block: x = roi, y = half (128 channels). 224 threads = 7 warps, warp = ph.
#define OPAD 52   // smem row stride (words) for 49 bins: 2-way conflicts max

__global__ void __launch_bounds__(224) roipool_main(const float* __restrict__ rois,
                                                    float* __restrict__ out) {
    __shared__ int sWs[PW], sWe[PW], sHs[PH], sHe[PH];
    __shared__ int sBase;
    __shared__ float sOut[128 * OPAD];

    int r    = blockIdx.x;
    int half = blockIdx.y;
    int tid  = threadIdx.x;
    int wid  = tid >> 5;                 // 0..6 == ph
    int lane = tid & 31;

    // ---- per-RoI bin edges (threads 0..6) ----
    if (tid < PW) {
        const float* roi = rois + r * 5;
        float f0 = roi[0], f1 = roi[1], f2 = roi[2], f3 = roi[3], f4 = roi[4];
        int x1 = (int)rintf(f1 * SCALE);
        int y1 = (int)rintf(f2 * SCALE);
        int x2 = (int)rintf(f3 * SCALE);
        int y2 = (int)rintf(f4 * SCALE);
        int rw = max(x2 - x1 + 1, 1);
        int rh = max(y2 - y1 + 1, 1);
        float bw = (float)rw * (1.0f / PW);
        float bh = (float)rh * (1.0f / PH);
        int j = tid;
        sWs[j] = min(max((int)floorf((float)j * bw) + x1, 0), W_);
        sWe[j] = min(max((int)ceilf((float)(j + 1) * bw) + x1, 0), W_);
        sHs[j] = min(max((int)floorf((float)j * bh) + y1, 0), H_);
        sHe[j] = min(max((int)ceilf((float)(j + 1) * bh) + y1, 0), H_);
        if (tid == 0) sBase = (int)f0 * (CHW_ / 4);   // in float4 units
    }
    __syncthreads();

    // ---- pooling: warp wid = ph; lane = channel quad ----
    int c4 = half * 32 + lane;           // float4 index within cell
    const float4* baseT = (const float4*)g_inT + sBase + c4;
    int h0 = sHs[wid];
    int h1 = sHe[wid];

#pragma unroll
    for (int pw = 0; pw < PW; ++pw) {
        int ws = sWs[pw];
        int we = sWe[pw];
        float4 a = make_float4(-INFINITY, -INFINITY, -INFINITY, -INFINITY);
        for (int h = h0; h < h1; ++h) {
            const float4* rp = baseT + (h * W_ + ws) * C4_;
            for (int w = ws; w < we; ++w) {
                float4 v = *rp;
                a.x = fmaxf(a.x, v.x);
                a.y = fmaxf(a.y, v.y);
                a.z = fmaxf(a.z, v.z);
                a.w = fmaxf(a.w, v.w);
                rp += C4_;
            }
        }
        if (h1 <= h0 || we <= ws) a = make_float4(0.f, 0.f, 0.f, 0.f);
        int bin = wid * PW + pw;
        int cc = lane * 4;
        sOut[(cc + 0) * OPAD + bin] = a.x;
        sOut[(cc + 1) * OPAD + bin] = a.y;
        sOut[(cc + 2) * OPAD + bin] = a.z;
        sOut[(cc + 3) * OPAD + bin] = a.w;
    }
    __syncthreads();

    // ---- coalesced copyout: out[r][half*128 + cc][bin] ----
    float* outp = out + ((size_t)r * C_ + half * 128) * BINS;
    for (int e = tid; e < 128 * BINS; e += 224) {
        u32 cc  = (u32)e / BINS;         // compiler magic-div
        u32 bin = (u32)e - cc * BINS;
        outp[e] = sOut[cc * OPAD + bin];
    }
}

// ---------------- launch ----------------
extern "C" void kernel_launch(void* const* d_in, const int* in_sizes, int n_in,
                              void* d_out, int out_size) {
    const float* input = (const float*)d_in[0];
    const float* rois  = (const float*)d_in[1];
    float* out = (float*)d_out;

    int N = in_sizes[0] / CHW_;
    int R = in_sizes[1] / 5;

    dim3 tg((HW_ + 31) / 32, C_ / 32, N);
    transpose_k<<<tg, dim3(32, 8)>>>(input);

    roipool_main<<<dim3(R, 2), 224>>>(rois, out);
}